// round 10
// baseline (speedup 1.0000x reference)
#include <cuda_runtime.h>
#include <cuda_fp16.h>
#include <cstdint>

// Problem constants
#define NROWS 4096
#define DIM   256
#define NBLK  32            // 4096 / 128
#define NTRI  528           // NBLK*(NBLK+1)/2
#define LOG2E10 14.42695040888963f

// ---------------- device scratch (no allocations allowed) ----------------
__device__ __align__(16) __half g_Zn[2ull * NROWS * DIM]; // [view][row][dim], fp16
__device__ float g_pos[NROWS];
__device__ float g_rowsum[2 * NBLK * NROWS];   // [view][colblock][row]
__device__ float g_part[2 * NBLK];             // per-rowblock partial sums
__device__ int   g_rowcnt[2 * NBLK];           // slices completed per rowblock
__device__ int   g_ticket;

__device__ __forceinline__ float fast_ex2(float x) {
    float y;
    asm("ex2.approx.ftz.f32 %0, %1;" : "=f"(y) : "f"(x));
    return y;
}

// ---------------- kernel 1: normalize rows (2 rows/warp), compute pos ------
__global__ void normalize_kernel(const float* __restrict__ zi, const float* __restrict__ zj) {
    if (blockIdx.x == 0) {
        if (threadIdx.x < 2 * NBLK) g_rowcnt[threadIdx.x] = 0;
        if (threadIdx.x == 2 * NBLK) g_ticket = 0;
    }

    int warp = threadIdx.x >> 5;
    int lane = threadIdx.x & 31;
    int row0 = (blockIdx.x * 8 + warp) * 2;    // rows row0, row0+1

    const float4* zi0 = reinterpret_cast<const float4*>(zi + (size_t)row0 * DIM);
    const float4* zj0 = reinterpret_cast<const float4*>(zj + (size_t)row0 * DIM);
    const float4* zi1 = reinterpret_cast<const float4*>(zi + (size_t)(row0 + 1) * DIM);
    const float4* zj1 = reinterpret_cast<const float4*>(zj + (size_t)(row0 + 1) * DIM);

    // 8 independent loads in flight (MLP 8)
    float4 A0a = zi0[lane * 2], A0b = zi0[lane * 2 + 1];
    float4 B0a = zj0[lane * 2], B0b = zj0[lane * 2 + 1];
    float4 A1a = zi1[lane * 2], A1b = zi1[lane * 2 + 1];
    float4 B1a = zj1[lane * 2], B1b = zj1[lane * 2 + 1];

    float si0 = A0a.x*A0a.x + A0a.y*A0a.y + A0a.z*A0a.z + A0a.w*A0a.w
              + A0b.x*A0b.x + A0b.y*A0b.y + A0b.z*A0b.z + A0b.w*A0b.w;
    float sj0 = B0a.x*B0a.x + B0a.y*B0a.y + B0a.z*B0a.z + B0a.w*B0a.w
              + B0b.x*B0b.x + B0b.y*B0b.y + B0b.z*B0b.z + B0b.w*B0b.w;
    float dd0 = A0a.x*B0a.x + A0a.y*B0a.y + A0a.z*B0a.z + A0a.w*B0a.w
              + A0b.x*B0b.x + A0b.y*B0b.y + A0b.z*B0b.z + A0b.w*B0b.w;
    float si1 = A1a.x*A1a.x + A1a.y*A1a.y + A1a.z*A1a.z + A1a.w*A1a.w
              + A1b.x*A1b.x + A1b.y*A1b.y + A1b.z*A1b.z + A1b.w*A1b.w;
    float sj1 = B1a.x*B1a.x + B1a.y*B1a.y + B1a.z*B1a.z + B1a.w*B1a.w
              + B1b.x*B1b.x + B1b.y*B1b.y + B1b.z*B1b.z + B1b.w*B1b.w;
    float dd1 = A1a.x*B1a.x + A1a.y*B1a.y + A1a.z*B1a.z + A1a.w*B1a.w
              + A1b.x*B1b.x + A1b.y*B1b.y + A1b.z*B1b.z + A1b.w*B1b.w;

    #pragma unroll
    for (int o = 16; o; o >>= 1) {
        si0 += __shfl_xor_sync(0xffffffffu, si0, o);
        sj0 += __shfl_xor_sync(0xffffffffu, sj0, o);
        dd0 += __shfl_xor_sync(0xffffffffu, dd0, o);
        si1 += __shfl_xor_sync(0xffffffffu, si1, o);
        sj1 += __shfl_xor_sync(0xffffffffu, sj1, o);
        dd1 += __shfl_xor_sync(0xffffffffu, dd1, o);
    }
    float rsI0 = rsqrtf(si0), rsJ0 = rsqrtf(sj0);
    float rsI1 = rsqrtf(si1), rsJ1 = rsqrtf(sj1);

    uint4* Z0 = reinterpret_cast<uint4*>(g_Zn);                       // view 0 = z_j
    uint4* Z1 = reinterpret_cast<uint4*>(g_Zn + (size_t)NROWS * DIM); // view 1 = z_i
    {
        __half2 p0 = __floats2half2_rn(B0a.x * rsJ0, B0a.y * rsJ0);
        __half2 p1 = __floats2half2_rn(B0a.z * rsJ0, B0a.w * rsJ0);
        __half2 p2 = __floats2half2_rn(B0b.x * rsJ0, B0b.y * rsJ0);
        __half2 p3 = __floats2half2_rn(B0b.z * rsJ0, B0b.w * rsJ0);
        uint4 u = { *reinterpret_cast<unsigned*>(&p0), *reinterpret_cast<unsigned*>(&p1),
                    *reinterpret_cast<unsigned*>(&p2), *reinterpret_cast<unsigned*>(&p3) };
        Z0[((size_t)row0 * DIM + lane * 8) / 8] = u;
    }
    {
        __half2 p0 = __floats2half2_rn(B1a.x * rsJ1, B1a.y * rsJ1);
        __half2 p1 = __floats2half2_rn(B1a.z * rsJ1, B1a.w * rsJ1);
        __half2 p2 = __floats2half2_rn(B1b.x * rsJ1, B1b.y * rsJ1);
        __half2 p3 = __floats2half2_rn(B1b.z * rsJ1, B1b.w * rsJ1);
        uint4 u = { *reinterpret_cast<unsigned*>(&p0), *reinterpret_cast<unsigned*>(&p1),
                    *reinterpret_cast<unsigned*>(&p2), *reinterpret_cast<unsigned*>(&p3) };
        Z0[((size_t)(row0 + 1) * DIM + lane * 8) / 8] = u;
    }
    {
        __half2 p0 = __floats2half2_rn(A0a.x * rsI0, A0a.y * rsI0);
        __half2 p1 = __floats2half2_rn(A0a.z * rsI0, A0a.w * rsI0);
        __half2 p2 = __floats2half2_rn(A0b.x * rsI0, A0b.y * rsI0);
        __half2 p3 = __floats2half2_rn(A0b.z * rsI0, A0b.w * rsI0);
        uint4 u = { *reinterpret_cast<unsigned*>(&p0), *reinterpret_cast<unsigned*>(&p1),
                    *reinterpret_cast<unsigned*>(&p2), *reinterpret_cast<unsigned*>(&p3) };
        Z1[((size_t)row0 * DIM + lane * 8) / 8] = u;
    }
    {
        __half2 p0 = __floats2half2_rn(A1a.x * rsI1, A1a.y * rsI1);
        __half2 p1 = __floats2half2_rn(A1a.z * rsI1, A1a.w * rsI1);
        __half2 p2 = __floats2half2_rn(A1b.x * rsI1, A1b.y * rsI1);
        __half2 p3 = __floats2half2_rn(A1b.z * rsI1, A1b.w * rsI1);
        uint4 u = { *reinterpret_cast<unsigned*>(&p0), *reinterpret_cast<unsigned*>(&p1),
                    *reinterpret_cast<unsigned*>(&p2), *reinterpret_cast<unsigned*>(&p3) };
        Z1[((size_t)(row0 + 1) * DIM + lane * 8) / 8] = u;
    }
    if (lane == 0) {
        g_pos[row0]     = dd0 * rsI0 * rsJ0;
        g_pos[row0 + 1] = dd1 * rsI1 * rsJ1;
    }
}

// ---------------- kernel 2: triangular Gram + inline finalize --------------
// f16 mma.sync m16n8k16 (f16 accum), ldmatrix loads, 3-stage cp.async
// pipeline. Each rowblock's lse is computed by the CTA that delivers its
// 32nd colblock slice; the 64th rowblock finisher emits the scalar loss.
__global__ __launch_bounds__(256, 2) void gram_kernel(float* __restrict__ out) {
    const int v = blockIdx.y;

    int t = blockIdx.x, bm = 0, rem = NBLK;
    while (t >= rem) { t -= rem; ++bm; --rem; }
    const int bn = bm + t;
    const bool diag = (bm == bn);

    __shared__ __align__(16) __half As[3][128 * 40];
    __shared__ __align__(16) __half Bs[3][128 * 40];
    __shared__ float s_rowsum[128];
    __shared__ float s_colsum[128];
    __shared__ float s_red[128];
    __shared__ int   s_fin[2];

    const int tid  = threadIdx.x;
    const int lane = tid & 31;
    const int w    = tid >> 5;
    const int warpM = w >> 2;        // 0..1
    const int warpN = w & 3;         // 0..3
    const int gid  = lane >> 2;      // 0..7
    const int tig  = lane & 3;       // 0..3

    if (tid < 128) { s_rowsum[tid] = 0.0f; s_colsum[tid] = 0.0f; }

    const __half* Zv = g_Zn + (size_t)v * NROWS * DIM;
    const __half* Ag = Zv + (size_t)bm * 128 * DIM;
    const __half* Bg = Zv + (size_t)bn * 128 * DIM;

    unsigned d16[4][4][2];
    #pragma unroll
    for (int mt = 0; mt < 4; ++mt)
        #pragma unroll
        for (int nt = 0; nt < 4; ++nt) { d16[mt][nt][0] = 0u; d16[mt][nt][1] = 0u; }

    const unsigned aLaneOff = (unsigned)(((lane & 15) * 40 + (lane >> 4) * 8) * 2);
    const unsigned bLaneOff = (unsigned)(((((lane >> 4) * 8) + (lane & 7)) * 40 + ((lane >> 3) & 1) * 8) * 2);
    unsigned sAb[3], sBb[3];
    #pragma unroll
    for (int s = 0; s < 3; ++s) {
        sAb[s] = (unsigned)__cvta_generic_to_shared(&As[s][0]) + aLaneOff + (unsigned)(warpM * 64 * 80);
        sBb[s] = (unsigned)__cvta_generic_to_shared(&Bs[s][0]) + bLaneOff + (unsigned)(warpN * 32 * 80);
    }

    #define LOAD_STAGE(buf, k0)                                                         \
        do {                                                                            \
            _Pragma("unroll")                                                           \
            for (int p = 0; p < 2; ++p) {                                               \
                int c  = tid + p * 256;                                                 \
                int r  = c >> 2;                                                        \
                int cp = c & 3;                                                         \
                const void* ga = Ag + r * DIM + (k0) + cp * 8;                          \
                unsigned sa = (unsigned)__cvta_generic_to_shared(&As[buf][r * 40 + cp * 8]); \
                asm volatile("cp.async.cg.shared.global [%0], [%1], 16;\n" ::           \
                             "r"(sa), "l"(ga));                                         \
                const void* gb = Bg + r * DIM + (k0) + cp * 8;                          \
                unsigned sb = (unsigned)__cvta_generic_to_shared(&Bs[buf][r * 40 + cp * 8]); \
                asm volatile("cp.async.cg.shared.global [%0], [%1], 16;\n" ::           \
                             "r"(sb), "l"(gb));                                         \
            }                                                                           \
            asm volatile("cp.async.commit_group;\n");                                   \
        } while (0)

    LOAD_STAGE(0, 0);

    int buf = 0;
    #pragma unroll
    for (int kt = 0; kt < 8; ++kt) {
        if (kt < 7) {
            int nb = buf + 1; if (nb == 3) nb = 0;
            LOAD_STAGE(nb, (kt + 1) * 32);
            asm volatile("cp.async.wait_group 1;\n");
        } else {
            asm volatile("cp.async.wait_group 0;\n");
        }
        __syncthreads();

        const unsigned aBase = sAb[buf];
        const unsigned bBase = sBb[buf];

        #pragma unroll
        for (int ks = 0; ks < 2; ++ks) {
            unsigned a[4][4], b[4][2];
            #pragma unroll
            for (int mt = 0; mt < 4; ++mt) {
                unsigned addr = aBase + (unsigned)(mt * 16 * 80 + ks * 32);
                asm volatile("ldmatrix.sync.aligned.m8n8.x4.shared.b16 {%0,%1,%2,%3}, [%4];\n"
                             : "=r"(a[mt][0]), "=r"(a[mt][1]), "=r"(a[mt][2]), "=r"(a[mt][3])
                             : "r"(addr));
            }
            #pragma unroll
            for (int nt2 = 0; nt2 < 2; ++nt2) {
                unsigned addr = bBase + (unsigned)(nt2 * 16 * 80 + ks * 32);
                asm volatile("ldmatrix.sync.aligned.m8n8.x4.shared.b16 {%0,%1,%2,%3}, [%4];\n"
                             : "=r"(b[nt2 * 2][0]), "=r"(b[nt2 * 2][1]),
                               "=r"(b[nt2 * 2 + 1][0]), "=r"(b[nt2 * 2 + 1][1])
                             : "r"(addr));
            }
            #pragma unroll
            for (int mt = 0; mt < 4; ++mt)
                #pragma unroll
                for (int nt = 0; nt < 4; ++nt)
                    asm volatile(
                        "mma.sync.aligned.m16n8k16.row.col.f16.f16.f16.f16 "
                        "{%0,%1}, {%2,%3,%4,%5}, {%6,%7}, {%0,%1};\n"
                        : "+r"(d16[mt][nt][0]), "+r"(d16[mt][nt][1])
                        : "r"(a[mt][0]), "r"(a[mt][1]), "r"(a[mt][2]), "r"(a[mt][3]),
                          "r"(b[nt][0]), "r"(b[nt][1]));
        }
        ++buf; if (buf == 3) buf = 0;
    }

    // epilogue: exp(10*d - 10); row sums + (off-diag) col sums
    float cs_e[4], cs_o[4];
    #pragma unroll
    for (int nt = 0; nt < 4; ++nt) { cs_e[nt] = 0.0f; cs_o[nt] = 0.0f; }

    #pragma unroll
    for (int mt = 0; mt < 4; ++mt) {
        float s1 = 0.0f, s2 = 0.0f;
        #pragma unroll
        for (int nt = 0; nt < 4; ++nt) {
            float2 lo = __half22float2(*reinterpret_cast<__half2*>(&d16[mt][nt][0]));
            float2 hi = __half22float2(*reinterpret_cast<__half2*>(&d16[mt][nt][1]));
            float e0 = fast_ex2(fmaf(lo.x, LOG2E10, -LOG2E10));
            float e1 = fast_ex2(fmaf(lo.y, LOG2E10, -LOG2E10));
            float e2 = fast_ex2(fmaf(hi.x, LOG2E10, -LOG2E10));
            float e3 = fast_ex2(fmaf(hi.y, LOG2E10, -LOG2E10));
            s1 += e0 + e1;
            s2 += e2 + e3;
            cs_e[nt] += e0 + e2;
            cs_o[nt] += e1 + e3;
        }
        s1 += __shfl_xor_sync(0xffffffffu, s1, 1);
        s1 += __shfl_xor_sync(0xffffffffu, s1, 2);
        s2 += __shfl_xor_sync(0xffffffffu, s2, 1);
        s2 += __shfl_xor_sync(0xffffffffu, s2, 2);
        if (tig == 0) {
            atomicAdd(&s_rowsum[warpM * 64 + mt * 16 + gid],     s1);
            atomicAdd(&s_rowsum[warpM * 64 + mt * 16 + gid + 8], s2);
        }
    }
    if (!diag) {
        #pragma unroll
        for (int nt = 0; nt < 4; ++nt) {
            #pragma unroll
            for (int o = 4; o <= 16; o <<= 1) {
                cs_e[nt] += __shfl_xor_sync(0xffffffffu, cs_e[nt], o);
                cs_o[nt] += __shfl_xor_sync(0xffffffffu, cs_o[nt], o);
            }
        }
        if (gid == 0) {
            #pragma unroll
            for (int nt = 0; nt < 4; ++nt) {
                atomicAdd(&s_colsum[warpN * 32 + nt * 8 + tig * 2],     cs_e[nt]);
                atomicAdd(&s_colsum[warpN * 32 + nt * 8 + tig * 2 + 1], cs_o[nt]);
            }
        }
    }
    __syncthreads();
    if (tid < 128) {
        g_rowsum[((size_t)v * NBLK + bn) * NROWS + bm * 128 + tid] = s_rowsum[tid];
        if (!diag)
            g_rowsum[((size_t)v * NBLK + bm) * NROWS + bn * 128 + tid] = s_colsum[tid];
    }
    __syncthreads();

    // ---- inline finalize: counter per rowblock; last slice-writer reduces --
    if (tid == 0) {
        __threadfence();   // release our g_rowsum slices
        int c0 = atomicAdd(&g_rowcnt[v * NBLK + bm], 1);
        s_fin[0] = (c0 == NBLK - 1) ? bm : -1;
        int f1 = -1;
        if (!diag) {
            int c1 = atomicAdd(&g_rowcnt[v * NBLK + bn], 1);
            if (c1 == NBLK - 1) f1 = bn;
        }
        s_fin[1] = f1;
    }
    __syncthreads();

    #pragma unroll
    for (int q = 0; q < 2; ++q) {
        int rb = s_fin[q];
        if (rb < 0) continue;
        __threadfence();   // acquire all 32 slices of rowblock rb
        float term = 0.0f;
        if (tid < 128) {
            int row = rb * 128 + tid;
            float s = 0.0f;
            #pragma unroll
            for (int b = 0; b < NBLK; ++b)
                s += g_rowsum[((size_t)v * NBLK + b) * NROWS + row];
            float p10 = 10.0f * g_pos[row];
            float A = s - 1.0f + __expf(p10 - 10.0f);
            term = 10.0f + logf(A) - p10;         // lse - pos
            s_red[tid] = term;
        }
        __syncthreads();
        #pragma unroll
        for (int o = 64; o; o >>= 1) {
            if (tid < o) s_red[tid] += s_red[tid + o];
            __syncthreads();
        }
        if (tid == 0) {
            g_part[v * NBLK + rb] = s_red[0];
            __threadfence();
            int tk = atomicAdd(&g_ticket, 1);
            if (tk == 2 * NBLK - 1) {
                __threadfence();
                float tot = 0.0f;
                #pragma unroll
                for (int b = 0; b < 2 * NBLK; ++b) tot += g_part[b];
                out[0] = tot / 8192.0f;
            }
        }
        __syncthreads();
    }
}

// ---------------- launch ---------------------------------------------------
extern "C" void kernel_launch(void* const* d_in, const int* in_sizes, int n_in,
                              void* d_out, int out_size) {
    const float* zi = (const float*)d_in[0];   // z_i
    const float* zj = (const float*)d_in[1];   // z_j

    normalize_kernel<<<NROWS / 16, 256>>>(zi, zj);
    gram_kernel<<<dim3(NTRI, 2), 256>>>((float*)d_out);
}

// round 13
// speedup vs baseline: 1.2128x; 1.2128x over previous
#include <cuda_runtime.h>
#include <cuda_fp16.h>
#include <cstdint>

// Problem constants
#define NROWS 4096
#define DIM   256
#define NBLK  32            // 4096 / 128
#define NTRI  528           // NBLK*(NBLK+1)/2
#define LOG2E10 14.42695040888963f

// gram smem: K-chunk 64, rows padded to 72 halfs (144B)
#define ROWP 72
#define STAGE_BYTES (128 * ROWP * 2)          // 18432 per tile per stage
#define GRAM_SMEM (4 * STAGE_BYTES + 1024)    // A[2] + B[2] + reductions

// ---------------- device scratch (no allocations allowed) ----------------
__device__ __align__(16) __half g_Zn[2ull * NROWS * DIM]; // [view][row][dim], fp16
__device__ float g_pos[NROWS];
__device__ float g_rowsum[2 * NBLK * NROWS];   // [view][colblock][row]
__device__ float g_blocksum[32];
__device__ int   g_ticket;

__device__ __forceinline__ float fast_ex2(float x) {
    float y;
    asm("ex2.approx.ftz.f32 %0, %1;" : "=f"(y) : "f"(x));
    return y;
}

// ---------------- kernel 1: normalize rows (2 rows/warp), compute pos ------
__global__ void normalize_kernel(const float* __restrict__ zi, const float* __restrict__ zj) {
    if (blockIdx.x == 0 && threadIdx.x == 0) g_ticket = 0;

    int warp = threadIdx.x >> 5;
    int lane = threadIdx.x & 31;
    int row0 = (blockIdx.x * 8 + warp) * 2;    // rows row0, row0+1

    const float4* zi0 = reinterpret_cast<const float4*>(zi + (size_t)row0 * DIM);
    const float4* zj0 = reinterpret_cast<const float4*>(zj + (size_t)row0 * DIM);
    const float4* zi1 = reinterpret_cast<const float4*>(zi + (size_t)(row0 + 1) * DIM);
    const float4* zj1 = reinterpret_cast<const float4*>(zj + (size_t)(row0 + 1) * DIM);

    float4 A0a = zi0[lane * 2], A0b = zi0[lane * 2 + 1];
    float4 B0a = zj0[lane * 2], B0b = zj0[lane * 2 + 1];
    float4 A1a = zi1[lane * 2], A1b = zi1[lane * 2 + 1];
    float4 B1a = zj1[lane * 2], B1b = zj1[lane * 2 + 1];

    float si0 = A0a.x*A0a.x + A0a.y*A0a.y + A0a.z*A0a.z + A0a.w*A0a.w
              + A0b.x*A0b.x + A0b.y*A0b.y + A0b.z*A0b.z + A0b.w*A0b.w;
    float sj0 = B0a.x*B0a.x + B0a.y*B0a.y + B0a.z*B0a.z + B0a.w*B0a.w
              + B0b.x*B0b.x + B0b.y*B0b.y + B0b.z*B0b.z + B0b.w*B0b.w;
    float dd0 = A0a.x*B0a.x + A0a.y*B0a.y + A0a.z*B0a.z + A0a.w*B0a.w
              + A0b.x*B0b.x + A0b.y*B0b.y + A0b.z*B0b.z + A0b.w*B0b.w;
    float si1 = A1a.x*A1a.x + A1a.y*A1a.y + A1a.z*A1a.z + A1a.w*A1a.w
              + A1b.x*A1b.x + A1b.y*A1b.y + A1b.z*A1b.z + A1b.w*A1b.w;
    float sj1 = B1a.x*B1a.x + B1a.y*B1a.y + B1a.z*B1a.z + B1a.w*B1a.w
              + B1b.x*B1b.x + B1b.y*B1b.y + B1b.z*B1b.z + B1b.w*B1b.w;
    float dd1 = A1a.x*B1a.x + A1a.y*B1a.y + A1a.z*B1a.z + A1a.w*B1a.w
              + A1b.x*B1b.x + A1b.y*B1b.y + A1b.z*B1b.z + A1b.w*B1b.w;

    #pragma unroll
    for (int o = 16; o; o >>= 1) {
        si0 += __shfl_xor_sync(0xffffffffu, si0, o);
        sj0 += __shfl_xor_sync(0xffffffffu, sj0, o);
        dd0 += __shfl_xor_sync(0xffffffffu, dd0, o);
        si1 += __shfl_xor_sync(0xffffffffu, si1, o);
        sj1 += __shfl_xor_sync(0xffffffffu, sj1, o);
        dd1 += __shfl_xor_sync(0xffffffffu, dd1, o);
    }
    float rsI0 = rsqrtf(si0), rsJ0 = rsqrtf(sj0);
    float rsI1 = rsqrtf(si1), rsJ1 = rsqrtf(sj1);

    uint4* Z0 = reinterpret_cast<uint4*>(g_Zn);                       // view 0 = z_j
    uint4* Z1 = reinterpret_cast<uint4*>(g_Zn + (size_t)NROWS * DIM); // view 1 = z_i
    {
        __half2 p0 = __floats2half2_rn(B0a.x * rsJ0, B0a.y * rsJ0);
        __half2 p1 = __floats2half2_rn(B0a.z * rsJ0, B0a.w * rsJ0);
        __half2 p2 = __floats2half2_rn(B0b.x * rsJ0, B0b.y * rsJ0);
        __half2 p3 = __floats2half2_rn(B0b.z * rsJ0, B0b.w * rsJ0);
        uint4 u = { *reinterpret_cast<unsigned*>(&p0), *reinterpret_cast<unsigned*>(&p1),
                    *reinterpret_cast<unsigned*>(&p2), *reinterpret_cast<unsigned*>(&p3) };
        Z0[((size_t)row0 * DIM + lane * 8) / 8] = u;
    }
    {
        __half2 p0 = __floats2half2_rn(B1a.x * rsJ1, B1a.y * rsJ1);
        __half2 p1 = __floats2half2_rn(B1a.z * rsJ1, B1a.w * rsJ1);
        __half2 p2 = __floats2half2_rn(B1b.x * rsJ1, B1b.y * rsJ1);
        __half2 p3 = __floats2half2_rn(B1b.z * rsJ1, B1b.w * rsJ1);
        uint4 u = { *reinterpret_cast<unsigned*>(&p0), *reinterpret_cast<unsigned*>(&p1),
                    *reinterpret_cast<unsigned*>(&p2), *reinterpret_cast<unsigned*>(&p3) };
        Z0[((size_t)(row0 + 1) * DIM + lane * 8) / 8] = u;
    }
    {
        __half2 p0 = __floats2half2_rn(A0a.x * rsI0, A0a.y * rsI0);
        __half2 p1 = __floats2half2_rn(A0a.z * rsI0, A0a.w * rsI0);
        __half2 p2 = __floats2half2_rn(A0b.x * rsI0, A0b.y * rsI0);
        __half2 p3 = __floats2half2_rn(A0b.z * rsI0, A0b.w * rsI0);
        uint4 u = { *reinterpret_cast<unsigned*>(&p0), *reinterpret_cast<unsigned*>(&p1),
                    *reinterpret_cast<unsigned*>(&p2), *reinterpret_cast<unsigned*>(&p3) };
        Z1[((size_t)row0 * DIM + lane * 8) / 8] = u;
    }
    {
        __half2 p0 = __floats2half2_rn(A1a.x * rsI1, A1a.y * rsI1);
        __half2 p1 = __floats2half2_rn(A1a.z * rsI1, A1a.w * rsI1);
        __half2 p2 = __floats2half2_rn(A1b.x * rsI1, A1b.y * rsI1);
        __half2 p3 = __floats2half2_rn(A1b.z * rsI1, A1b.w * rsI1);
        uint4 u = { *reinterpret_cast<unsigned*>(&p0), *reinterpret_cast<unsigned*>(&p1),
                    *reinterpret_cast<unsigned*>(&p2), *reinterpret_cast<unsigned*>(&p3) };
        Z1[((size_t)(row0 + 1) * DIM + lane * 8) / 8] = u;
    }
    if (lane == 0) {
        g_pos[row0]     = dd0 * rsI0 * rsJ0;
        g_pos[row0 + 1] = dd1 * rsI1 * rsJ1;
    }
}

// ---------------- kernel 2: triangular Gram, K-chunk 64, 2-stage -----------
// Upper-triangular 128x128 tiles (bm<=bn) per view; off-diagonal tiles also
// emit column sums. f16 mma.sync m16n8k16 (f16 accum); ldmatrix loads; 4
// syncthreads total (one per 64-wide K chunk).
__global__ __launch_bounds__(256, 2) void gram_kernel() {
    extern __shared__ unsigned char smem[];
    __half* As = reinterpret_cast<__half*>(smem);                       // [2][128*72]
    __half* Bs = reinterpret_cast<__half*>(smem + 2 * STAGE_BYTES);     // [2][128*72]
    float* s_rowsum = reinterpret_cast<float*>(smem + 4 * STAGE_BYTES);
    float* s_colsum = s_rowsum + 128;

    const int v = blockIdx.y;

    int t = blockIdx.x, bm = 0, rem = NBLK;
    while (t >= rem) { t -= rem; ++bm; --rem; }
    const int bn = bm + t;
    const bool diag = (bm == bn);

    const int tid  = threadIdx.x;
    const int lane = tid & 31;
    const int w    = tid >> 5;
    const int warpM = w >> 2;        // 0..1
    const int warpN = w & 3;         // 0..3
    const int gid  = lane >> 2;      // 0..7
    const int tig  = lane & 3;       // 0..3

    if (tid < 128) { s_rowsum[tid] = 0.0f; s_colsum[tid] = 0.0f; }

    const __half* Zv = g_Zn + (size_t)v * NROWS * DIM;
    const __half* Ag = Zv + (size_t)bm * 128 * DIM;
    const __half* Bg = Zv + (size_t)bn * 128 * DIM;

    unsigned d16[4][4][2];
    #pragma unroll
    for (int mt = 0; mt < 4; ++mt)
        #pragma unroll
        for (int nt = 0; nt < 4; ++nt) { d16[mt][nt][0] = 0u; d16[mt][nt][1] = 0u; }

    // ldmatrix per-lane offsets (bytes), 144B row stride
    const unsigned aLaneOff = (unsigned)((lane & 15) * 144 + (lane >> 4) * 16);
    const unsigned bLaneOff = (unsigned)(((lane >> 4) * 8 + (lane & 7)) * 144 + ((lane >> 3) & 1) * 16);
    unsigned sAb[2], sBb[2];
    #pragma unroll
    for (int s = 0; s < 2; ++s) {
        sAb[s] = (unsigned)__cvta_generic_to_shared(As) + (unsigned)(s * STAGE_BYTES)
               + aLaneOff + (unsigned)(warpM * 64 * 144);
        sBb[s] = (unsigned)__cvta_generic_to_shared(Bs) + (unsigned)(s * STAGE_BYTES)
               + bLaneOff + (unsigned)(warpN * 32 * 144);
    }

    // one stage = 128 rows x 64 halfs (128B) per tile; 8 x 16B chunks per row
    #define LOAD_STAGE(buf, k0)                                                          \
        do {                                                                             \
            _Pragma("unroll")                                                            \
            for (int p = 0; p < 4; ++p) {                                                \
                int idx = p * 256 + tid;                                                 \
                int r = idx >> 3, c = idx & 7;                                           \
                const void* ga = Ag + (size_t)r * DIM + (k0) + c * 8;                    \
                unsigned sa = (unsigned)__cvta_generic_to_shared(As)                     \
                            + (unsigned)((buf) * STAGE_BYTES + r * 144 + c * 16);        \
                asm volatile("cp.async.cg.shared.global [%0], [%1], 16;\n" ::            \
                             "r"(sa), "l"(ga));                                          \
                const void* gb = Bg + (size_t)r * DIM + (k0) + c * 8;                    \
                unsigned sb = (unsigned)__cvta_generic_to_shared(Bs)                     \
                            + (unsigned)((buf) * STAGE_BYTES + r * 144 + c * 16);        \
                asm volatile("cp.async.cg.shared.global [%0], [%1], 16;\n" ::            \
                             "r"(sb), "l"(gb));                                          \
            }                                                                            \
            asm volatile("cp.async.commit_group;\n");                                    \
        } while (0)

    LOAD_STAGE(0, 0);

    #pragma unroll
    for (int kt = 0; kt < 4; ++kt) {
        const int buf = kt & 1;
        asm volatile("cp.async.wait_group 0;\n");
        __syncthreads();            // stage `buf` ready; prior compute on buf done
        if (kt < 3) LOAD_STAGE(buf ^ 1, (kt + 1) * 64);

        const unsigned aBase = sAb[buf];
        const unsigned bBase = sBb[buf];

        #pragma unroll
        for (int ks = 0; ks < 4; ++ks) {
            unsigned a[4][4], b[4][2];
            #pragma unroll
            for (int mt = 0; mt < 4; ++mt) {
                unsigned addr = aBase + (unsigned)(mt * 16 * 144 + ks * 32);
                asm volatile("ldmatrix.sync.aligned.m8n8.x4.shared.b16 {%0,%1,%2,%3}, [%4];\n"
                             : "=r"(a[mt][0]), "=r"(a[mt][1]), "=r"(a[mt][2]), "=r"(a[mt][3])
                             : "r"(addr));
            }
            #pragma unroll
            for (int nt2 = 0; nt2 < 2; ++nt2) {
                unsigned addr = bBase + (unsigned)(nt2 * 16 * 144 + ks * 32);
                asm volatile("ldmatrix.sync.aligned.m8n8.x4.shared.b16 {%0,%1,%2,%3}, [%4];\n"
                             : "=r"(b[nt2 * 2][0]), "=r"(b[nt2 * 2][1]),
                               "=r"(b[nt2 * 2 + 1][0]), "=r"(b[nt2 * 2 + 1][1])
                             : "r"(addr));
            }
            #pragma unroll
            for (int mt = 0; mt < 4; ++mt)
                #pragma unroll
                for (int nt = 0; nt < 4; ++nt)
                    asm volatile(
                        "mma.sync.aligned.m16n8k16.row.col.f16.f16.f16.f16 "
                        "{%0,%1}, {%2,%3,%4,%5}, {%6,%7}, {%0,%1};\n"
                        : "+r"(d16[mt][nt][0]), "+r"(d16[mt][nt][1])
                        : "r"(a[mt][0]), "r"(a[mt][1]), "r"(a[mt][2]), "r"(a[mt][3]),
                          "r"(b[nt][0]), "r"(b[nt][1]));
        }
    }

    // epilogue: exp(10*d - 10); row sums + (off-diag) col sums
    float cs_e[4], cs_o[4];
    #pragma unroll
    for (int nt = 0; nt < 4; ++nt) { cs_e[nt] = 0.0f; cs_o[nt] = 0.0f; }

    #pragma unroll
    for (int mt = 0; mt < 4; ++mt) {
        float s1 = 0.0f, s2 = 0.0f;
        #pragma unroll
        for (int nt = 0; nt < 4; ++nt) {
            float2 lo = __half22float2(*reinterpret_cast<__half2*>(&d16[mt][nt][0]));
            float2 hi = __half22float2(*reinterpret_cast<__half2*>(&d16[mt][nt][1]));
            float e0 = fast_ex2(fmaf(lo.x, LOG2E10, -LOG2E10));
            float e1 = fast_ex2(fmaf(lo.y, LOG2E10, -LOG2E10));
            float e2 = fast_ex2(fmaf(hi.x, LOG2E10, -LOG2E10));
            float e3 = fast_ex2(fmaf(hi.y, LOG2E10, -LOG2E10));
            s1 += e0 + e1;
            s2 += e2 + e3;
            cs_e[nt] += e0 + e2;
            cs_o[nt] += e1 + e3;
        }
        s1 += __shfl_xor_sync(0xffffffffu, s1, 1);
        s1 += __shfl_xor_sync(0xffffffffu, s1, 2);
        s2 += __shfl_xor_sync(0xffffffffu, s2, 1);
        s2 += __shfl_xor_sync(0xffffffffu, s2, 2);
        if (tig == 0) {
            atomicAdd(&s_rowsum[warpM * 64 + mt * 16 + gid],     s1);
            atomicAdd(&s_rowsum[warpM * 64 + mt * 16 + gid + 8], s2);
        }
    }
    if (!diag) {
        #pragma unroll
        for (int nt = 0; nt < 4; ++nt) {
            #pragma unroll
            for (int o = 4; o <= 16; o <<= 1) {
                cs_e[nt] += __shfl_xor_sync(0xffffffffu, cs_e[nt], o);
                cs_o[nt] += __shfl_xor_sync(0xffffffffu, cs_o[nt], o);
            }
        }
        if (gid == 0) {
            #pragma unroll
            for (int nt = 0; nt < 4; ++nt) {
                atomicAdd(&s_colsum[warpN * 32 + nt * 8 + tig * 2],     cs_e[nt]);
                atomicAdd(&s_colsum[warpN * 32 + nt * 8 + tig * 2 + 1], cs_o[nt]);
            }
        }
    }
    __syncthreads();
    if (tid < 128) {
        g_rowsum[((size_t)v * NBLK + bn) * NROWS + bm * 128 + tid] = s_rowsum[tid];
        if (!diag)
            g_rowsum[((size_t)v * NBLK + bm) * NROWS + bn * 128 + tid] = s_colsum[tid];
    }
}

// ---------------- kernel 3: merged finalize (ticket) -----------------------
__global__ void finalize_kernel(float* __restrict__ out) {
    int tid = threadIdx.x;
    int gid = blockIdx.x * 256 + tid;         // 0..8191
    int v = gid >> 12;
    int i = gid & (NROWS - 1);

    float s = 0.0f;
    #pragma unroll
    for (int b = 0; b < NBLK; ++b)
        s += g_rowsum[((size_t)v * NBLK + b) * NROWS + i];

    float p10 = 10.0f * g_pos[i];
    float A = s - 1.0f + __expf(p10 - 10.0f);  // drop self term, add positive
    float term = 10.0f + logf(A) - p10;        // lse - pos

    __shared__ float red[256];
    red[tid] = term;
    __syncthreads();
    #pragma unroll
    for (int o = 128; o; o >>= 1) {
        if (tid < o) red[tid] += red[tid + o];
        __syncthreads();
    }
    if (tid == 0) {
        g_blocksum[blockIdx.x] = red[0];
        __threadfence();
        int tk = atomicAdd(&g_ticket, 1);
        if (tk == 31) {
            __threadfence();
            float tot = 0.0f;
            #pragma unroll
            for (int b = 0; b < 32; ++b) tot += g_blocksum[b];
            out[0] = tot / 8192.0f;
        }
    }
}

// ---------------- launch ---------------------------------------------------
extern "C" void kernel_launch(void* const* d_in, const int* in_sizes, int n_in,
                              void* d_out, int out_size) {
    const float* zi = (const float*)d_in[0];   // z_i
    const float* zj = (const float*)d_in[1];   // z_j

    cudaFuncSetAttribute(gram_kernel, cudaFuncAttributeMaxDynamicSharedMemorySize, GRAM_SMEM);

    normalize_kernel<<<NROWS / 16, 256>>>(zi, zj);
    gram_kernel<<<dim3(NTRI, 2), 256, GRAM_SMEM>>>();
    finalize_kernel<<<32, 256>>>((float*)d_out);
}